// round 15
// baseline (speedup 1.0000x reference)
#include <cuda_runtime.h>
#include <cuda_bf16.h>
#include <math.h>
#include <stdint.h>

// Problem constants (fixed by the dataset)
#define S_LEN 2048
#define NHEAD 16
#define HDIM  256
#define BATCH 2
#define DMODEL 4096
#define NTOK  4096              // BATCH * S_LEN
#define BH    32                // BATCH * NHEAD

// ---------------- scratch (device globals; no allocations allowed) ----------
__device__ float g_K [(size_t)NTOK * DMODEL];   // post-RoPE K (fp32, cache source)
__device__ float g_V [(size_t)NTOK * DMODEL];
__device__ float g_Sc[(size_t)BH * S_LEN * S_LEN]; // fp32 scores
__device__ int   g_idx[5][NTOK];
__device__ int   g_inv[2][NTOK];                // inverse cache maps (k, v)
// bf16 split buffers
__device__ __nv_bfloat16 g_Xh[(size_t)NTOK * DMODEL];   // hs splits, later O splits
__device__ __nv_bfloat16 g_Xl[(size_t)NTOK * DMODEL];
__device__ __nv_bfloat16 g_Qh[(size_t)NTOK * DMODEL];   // post-RoPE Q splits
__device__ __nv_bfloat16 g_Ql[(size_t)NTOK * DMODEL];
__device__ __nv_bfloat16 g_Wqh[(size_t)DMODEL * DMODEL];
__device__ __nv_bfloat16 g_Wql[(size_t)DMODEL * DMODEL];
__device__ __nv_bfloat16 g_Wkh[(size_t)DMODEL * DMODEL];
__device__ __nv_bfloat16 g_Wkl[(size_t)DMODEL * DMODEL];
__device__ __nv_bfloat16 g_Wvh[(size_t)DMODEL * DMODEL];
__device__ __nv_bfloat16 g_Wvl[(size_t)DMODEL * DMODEL];
__device__ __nv_bfloat16 g_Woh[(size_t)DMODEL * DMODEL];
__device__ __nv_bfloat16 g_Wol[(size_t)DMODEL * DMODEL];
__device__ __nv_bfloat16 g_Kgh[(size_t)NTOK * DMODEL];  // gathered K split [BH][S][HD]
__device__ __nv_bfloat16 g_Kgl[(size_t)NTOK * DMODEL];
__device__ __nv_bfloat16 g_Vth[(size_t)NTOK * DMODEL];  // V^T split: [BH][HD][S]
__device__ __nv_bfloat16 g_Vtl[(size_t)NTOK * DMODEL];
__device__ __nv_bfloat16 g_Ph[(size_t)BH * S_LEN * S_LEN];  // prob split
__device__ __nv_bfloat16 g_Pl[(size_t)BH * S_LEN * S_LEN];

// ============================================================================
// helpers
// ============================================================================
__device__ __forceinline__ uint32_t smem_u32(const void* p) {
    uint32_t a;
    asm("{ .reg .u64 t; cvta.to.shared.u64 t, %1; cvt.u32.u64 %0, t; }"
        : "=r"(a) : "l"(p));
    return a;
}
__device__ __forceinline__ void cp_async16(uint32_t dst, const void* src) {
    asm volatile("cp.async.cg.shared.global [%0], [%1], 16;"
                 :: "r"(dst), "l"(src) : "memory");
}
__device__ __forceinline__ void cp_commit() {
    asm volatile("cp.async.commit_group;" ::: "memory");
}
__device__ __forceinline__ void cp_wait1() {
    asm volatile("cp.async.wait_group 1;" ::: "memory");
}
__device__ __forceinline__ void mma_bf16(float* d, const uint32_t* a, const uint32_t* b) {
    asm volatile(
        "mma.sync.aligned.m16n8k16.row.col.f32.bf16.bf16.f32 "
        "{%0,%1,%2,%3}, {%4,%5,%6,%7}, {%8,%9}, {%0,%1,%2,%3};"
        : "+f"(d[0]), "+f"(d[1]), "+f"(d[2]), "+f"(d[3])
        : "r"(a[0]), "r"(a[1]), "r"(a[2]), "r"(a[3]), "r"(b[0]), "r"(b[1]));
}
__device__ __forceinline__ void ldsm_x4(uint32_t* r, uint32_t addr) {
    asm volatile("ldmatrix.sync.aligned.m8n8.x4.shared.b16 {%0,%1,%2,%3}, [%4];"
                 : "=r"(r[0]), "=r"(r[1]), "=r"(r[2]), "=r"(r[3]) : "r"(addr));
}
__device__ __forceinline__ __nv_bfloat162 split_hi2(float a, float b,
                                                    __nv_bfloat162& lo) {
    __nv_bfloat16 h0 = __float2bfloat16(a);
    __nv_bfloat16 h1 = __float2bfloat16(b);
    lo = __halves2bfloat162(__float2bfloat16(a - __bfloat162float(h0)),
                            __float2bfloat16(b - __bfloat162float(h1)));
    return __halves2bfloat162(h0, h1);
}

// ============================================================================
// shared bf16-split mma core: CTA tile 128(M) x 256(N) x 32(K), 8 warps (2x4),
// warp tile 64x64, 3-stage cp.async pipeline, 80B-padded smem rows.
// acc = Ah*Bh^T + Ah*Bl^T + Al*Bh^T over kiters*32 K elements.
// Fragment loads via ldmatrix.x4 (16 per k16 slice instead of 64 LDS.32).
// ============================================================================
#define GBM 128
#define GBN 256
#define GBK 32
#define ROWB 80
#define SM_A_SZ (GBM * ROWB)            // 10240
#define SM_B_SZ (GBN * ROWB)            // 20480
#define OFF_AH 0
#define OFF_AL SM_A_SZ
#define OFF_BH (2 * SM_A_SZ)
#define OFF_BL (2 * SM_A_SZ + SM_B_SZ)
#define STAGE_B (2 * SM_A_SZ + 2 * SM_B_SZ)  // 61440
#define PIPE 3
#define GEMM_SMEM (PIPE * STAGE_B)      // 184320

__device__ __forceinline__ void gemm_split_core(
    const __nv_bfloat16* __restrict__ Ah, const __nv_bfloat16* __restrict__ Al,
    const __nv_bfloat16* __restrict__ Bh, const __nv_bfloat16* __restrict__ Bl,
    int64_t lda, int64_t ldb, int kiters,
    char* sm, float acc[4][8][4])
{
    const uint32_t sbase = smem_u32(sm);
    const int tid  = threadIdx.x;
    const int lane = tid & 31;
    const int wid = tid >> 5;
    const int wm = wid >> 2, wn = wid & 3;

#pragma unroll
    for (int i = 0; i < 4; i++)
#pragma unroll
        for (int j = 0; j < 8; j++)
#pragma unroll
            for (int r = 0; r < 4; r++) acc[i][j][r] = 0.f;

    // ---- compressed cp.async addressing: 4 base pointers + strides ----
    const int arow = tid >> 2, akc = tid & 3;
    const __nv_bfloat16* srcAh = Ah + (int64_t)arow * lda + akc * 8;
    const __nv_bfloat16* srcAl = Al + (int64_t)arow * lda + akc * 8;
    const __nv_bfloat16* srcBh = Bh + (int64_t)arow * ldb + akc * 8;
    const __nv_bfloat16* srcBl = Bl + (int64_t)arow * ldb + akc * 8;
    const int64_t sa = 64 * lda;
    const int64_t sb = 64 * ldb;
    const uint32_t dbase = (uint32_t)(arow * ROWB + akc * 16);

    auto issue = [&](int s) {
        uint32_t dA = sbase + s * STAGE_B + dbase;
        cp_async16(dA + OFF_AH,             srcAh);
        cp_async16(dA + OFF_AH + 64 * ROWB, srcAh + sa);
        cp_async16(dA + OFF_AL,             srcAl);
        cp_async16(dA + OFF_AL + 64 * ROWB, srcAl + sa);
#pragma unroll
        for (int r = 0; r < 4; r++) {
            cp_async16(dA + OFF_BH + r * 64 * ROWB, srcBh + r * sb);
            cp_async16(dA + OFF_BL + r * 64 * ROWB, srcBl + r * sb);
        }
        srcAh += GBK; srcAl += GBK; srcBh += GBK; srcBl += GBK;
    };

    issue(0); cp_commit();
    issue(1); cp_commit();

    // ---- ldmatrix per-lane base offsets (within a stage) ----
    const int sub = lane >> 3;            // 0..3 (matrix id within x4)
    const int lr8 = lane & 7;
    const uint32_t a_off = (uint32_t)((wm * 64 + (sub & 1) * 8 + lr8) * ROWB
                                      + (sub >> 1) * 16);
    const uint32_t b_off = (uint32_t)((wn * 64 + (sub & 1) * 8 + lr8) * ROWB
                                      + (sub >> 1) * 16);

    for (int it = 0; it < kiters; it++) {
        cp_wait1();
        __syncthreads();
        const uint32_t stg = sbase + (it % PIPE) * STAGE_B;

#pragma unroll
        for (int ks = 0; ks < 2; ks++) {
            const uint32_t ka = stg + ks * 32;
            uint32_t ah[4][4], al[4][4], bh2[4][4], bl2[4][4];
#pragma unroll
            for (int i = 0; i < 4; i++)
                ldsm_x4(ah[i], ka + OFF_AH + a_off + i * (16 * ROWB));
#pragma unroll
            for (int jp = 0; jp < 4; jp++)
                ldsm_x4(bh2[jp], ka + OFF_BH + b_off + jp * (16 * ROWB));
            // bh2[jp] = {b(2jp)[0], b(2jp+1)[0], b(2jp)[1], b(2jp+1)[1]}
#pragma unroll
            for (int jp = 0; jp < 4; jp++) {
                uint32_t b0[2] = {bh2[jp][0], bh2[jp][2]};
                uint32_t b1[2] = {bh2[jp][1], bh2[jp][3]};
#pragma unroll
                for (int i = 0; i < 4; i++) {
                    mma_bf16(acc[i][2 * jp],     ah[i], b0);
                    mma_bf16(acc[i][2 * jp + 1], ah[i], b1);
                }
            }

#pragma unroll
            for (int jp = 0; jp < 4; jp++)
                ldsm_x4(bl2[jp], ka + OFF_BL + b_off + jp * (16 * ROWB));
#pragma unroll
            for (int jp = 0; jp < 4; jp++) {
                uint32_t b0[2] = {bl2[jp][0], bl2[jp][2]};
                uint32_t b1[2] = {bl2[jp][1], bl2[jp][3]};
#pragma unroll
                for (int i = 0; i < 4; i++) {
                    mma_bf16(acc[i][2 * jp],     ah[i], b0);
                    mma_bf16(acc[i][2 * jp + 1], ah[i], b1);
                }
            }

#pragma unroll
            for (int i = 0; i < 4; i++)
                ldsm_x4(al[i], ka + OFF_AL + a_off + i * (16 * ROWB));
#pragma unroll
            for (int jp = 0; jp < 4; jp++) {
                uint32_t b0[2] = {bh2[jp][0], bh2[jp][2]};
                uint32_t b1[2] = {bh2[jp][1], bh2[jp][3]};
#pragma unroll
                for (int i = 0; i < 4; i++) {
                    mma_bf16(acc[i][2 * jp],     al[i], b0);
                    mma_bf16(acc[i][2 * jp + 1], al[i], b1);
                }
            }
        }

        if (it + 2 < kiters) issue((it + 2) % PIPE);
        cp_commit();
    }
}

// ---------------- fused QKV projection GEMM + RoPE epilogue ------------------
// z=0: Q -> RoPE -> bf16 splits; z=1: K -> RoPE -> fp32; z=2: V -> fp32.
__global__ __launch_bounds__(256, 1)
void qkv_mma(const __nv_bfloat16* __restrict__ Xh, const __nv_bfloat16* __restrict__ Xl,
             const __nv_bfloat16* __restrict__ Wqh, const __nv_bfloat16* __restrict__ Wql,
             const __nv_bfloat16* __restrict__ Wkh, const __nv_bfloat16* __restrict__ Wkl,
             const __nv_bfloat16* __restrict__ Wvh, const __nv_bfloat16* __restrict__ Wvl,
             const int* __restrict__ pos_ids,
             __nv_bfloat16* __restrict__ Qh, __nv_bfloat16* __restrict__ Ql,
             float* __restrict__ K, float* __restrict__ V) {
    extern __shared__ __align__(16) char sm[];
    const int z = blockIdx.z;
    const int m0 = blockIdx.y * GBM, n0 = blockIdx.x * GBN;
    const __nv_bfloat16* Bh = (z == 0) ? Wqh : (z == 1) ? Wkh : Wvh;
    const __nv_bfloat16* Bl = (z == 0) ? Wql : (z == 1) ? Wkl : Wvl;
    float acc[4][8][4];
    gemm_split_core(Xh + (size_t)m0 * DMODEL, Xl + (size_t)m0 * DMODEL,
                    Bh + (size_t)n0 * DMODEL, Bl + (size_t)n0 * DMODEL,
                    DMODEL, DMODEL, DMODEL / GBK, sm, acc);

    const int lane = threadIdx.x & 31, wid = threadIdx.x >> 5;
    const int g = lane >> 2, t = lane & 3;
    const int wm = wid >> 2, wn = wid & 3;
    const bool do_rope = (z < 2) && (wn == 0);   // head-local cols 0..62

#pragma unroll
    for (int i = 0; i < 4; i++) {
        int m = m0 + wm * 64 + i * 16 + g;       // global token index
        float p0 = 0.f, p1 = 0.f;
        if (do_rope) {
            p0 = (float)pos_ids[m];
            p1 = (float)pos_ids[m + 8];
        }
#pragma unroll
        for (int j = 0; j < 8; j++) {
            int n = n0 + wn * 64 + j * 8 + t * 2;
            float v0 = acc[i][j][0], v1 = acc[i][j][1];
            float v2 = acc[i][j][2], v3 = acc[i][j][3];
            if (do_rope) {
                int f = j * 4 + t;
                // 10000^(-2f/64) = exp(-f * ln(10000)/32)
                float ivf = __expf(-0.28782313662425572f * (float)f);
                float s0, c0, s1, c1;
                __sincosf(p0 * ivf, &s0, &c0);
                __sincosf(p1 * ivf, &s1, &c1);
                float nv0 = c0 * v0 - s0 * v1, nv1 = s0 * v0 + c0 * v1;
                float nv2 = c1 * v2 - s1 * v3, nv3 = s1 * v2 + c1 * v3;
                v0 = nv0; v1 = nv1; v2 = nv2; v3 = nv3;
            }
            if (z == 0) {
                __nv_bfloat162 lo0, lo1;
                __nv_bfloat162 hi0 = split_hi2(v0, v1, lo0);
                __nv_bfloat162 hi1 = split_hi2(v2, v3, lo1);
                *(__nv_bfloat162*)&Qh[(size_t)m * DMODEL + n]       = hi0;
                *(__nv_bfloat162*)&Ql[(size_t)m * DMODEL + n]       = lo0;
                *(__nv_bfloat162*)&Qh[(size_t)(m + 8) * DMODEL + n] = hi1;
                *(__nv_bfloat162*)&Ql[(size_t)(m + 8) * DMODEL + n] = lo1;
            } else {
                float* C = (z == 1) ? K : V;
                *(float2*)&C[(size_t)m * DMODEL + n]       = make_float2(v0, v1);
                *(float2*)&C[(size_t)(m + 8) * DMODEL + n] = make_float2(v2, v3);
            }
        }
    }
}

// ---------------- QK^T GEMM: causal mask + scale + attention mask -----------
__global__ __launch_bounds__(256, 1)
void qk_mma(const __nv_bfloat16* __restrict__ Qh, const __nv_bfloat16* __restrict__ Ql,
            const __nv_bfloat16* __restrict__ Kh, const __nv_bfloat16* __restrict__ Kl,
            const float* __restrict__ am, float* __restrict__ Sc) {
    extern __shared__ __align__(16) char sm[];
    const int bh = blockIdx.z;
    const int b = bh >> 4, h = bh & 15;
    const int m0 = blockIdx.y * GBM, n0 = blockIdx.x * GBN;
    if (n0 > m0 + (GBM - 1)) return;   // fully masked: softmax never reads it

    float* Cb = Sc + (size_t)bh * S_LEN * S_LEN;
    const size_t aoff = (size_t)b * S_LEN * DMODEL + (size_t)h * HDIM + (size_t)m0 * DMODEL;
    const size_t boff = (size_t)bh * S_LEN * HDIM + (size_t)n0 * HDIM;
    float acc[4][8][4];
    gemm_split_core(Qh + aoff, Ql + aoff, Kh + boff, Kl + boff,
                    DMODEL, HDIM, HDIM / GBK, sm, acc);

    const int lane = threadIdx.x & 31, wid = threadIdx.x >> 5;
    const int g = lane >> 2, t = lane & 3;
    const int wm = wid >> 2, wn = wid & 3;
    const float scale = 1.0f / 16.0f;
#pragma unroll
    for (int i = 0; i < 4; i++) {
        int m = m0 + wm * 64 + i * 16 + g;
#pragma unroll
        for (int j = 0; j < 8; j++) {
            int n = n0 + wn * 64 + j * 8 + t * 2;
            float amv0 = am[b * S_LEN + n], amv1 = am[b * S_LEN + n + 1];
            float v0 = (n     <= m) ? (acc[i][j][0] * scale + amv0) : -1e30f;
            float v1 = (n + 1 <= m) ? (acc[i][j][1] * scale + amv1) : -1e30f;
            float v2 = (n     <= m + 8) ? (acc[i][j][2] * scale + amv0) : -1e30f;
            float v3 = (n + 1 <= m + 8) ? (acc[i][j][3] * scale + amv1) : -1e30f;
            *(float2*)&Cb[(size_t)m * S_LEN + n]       = make_float2(v0, v1);
            *(float2*)&Cb[(size_t)(m + 8) * S_LEN + n] = make_float2(v2, v3);
        }
    }
}

// ---------------- PV GEMM -> bf16 split O epilogue ---------------------------
__global__ __launch_bounds__(256, 1)
void pv_mma(const __nv_bfloat16* __restrict__ Ph, const __nv_bfloat16* __restrict__ Pl,
            const __nv_bfloat16* __restrict__ Vth, const __nv_bfloat16* __restrict__ Vtl,
            __nv_bfloat16* __restrict__ Oh, __nv_bfloat16* __restrict__ Ol) {
    extern __shared__ __align__(16) char sm[];
    const int bh = blockIdx.z;
    const int b = bh >> 4, h = bh & 15;
    // reversed order: longest-running tiles (largest m0) launch first
    const int m0 = (gridDim.y - 1 - blockIdx.y) * GBM;
    const size_t aoff = (size_t)bh * S_LEN * S_LEN + (size_t)m0 * S_LEN;
    const size_t boff = (size_t)bh * HDIM * S_LEN;
    float acc[4][8][4];
    gemm_split_core(Ph + aoff, Pl + aoff, Vth + boff, Vtl + boff,
                    S_LEN, S_LEN, (m0 + GBM) / GBK, sm, acc);

    const int lane = threadIdx.x & 31, wid = threadIdx.x >> 5;
    const int g = lane >> 2, t = lane & 3;
    const int wm = wid >> 2, wn = wid & 3;
#pragma unroll
    for (int i = 0; i < 4; i++) {
        int m = m0 + wm * 64 + i * 16 + g;
        size_t tok0 = (size_t)b * S_LEN + m;
#pragma unroll
        for (int j = 0; j < 8; j++) {
            int n = wn * 64 + j * 8 + t * 2;
            __nv_bfloat162 lo0, lo1;
            __nv_bfloat162 hi0 = split_hi2(acc[i][j][0], acc[i][j][1], lo0);
            __nv_bfloat162 hi1 = split_hi2(acc[i][j][2], acc[i][j][3], lo1);
            *(__nv_bfloat162*)&Oh[tok0 * DMODEL + h * HDIM + n]       = hi0;
            *(__nv_bfloat162*)&Ol[tok0 * DMODEL + h * HDIM + n]       = lo0;
            *(__nv_bfloat162*)&Oh[(tok0 + 8) * DMODEL + h * HDIM + n] = hi1;
            *(__nv_bfloat162*)&Ol[(tok0 + 8) * DMODEL + h * HDIM + n] = lo1;
        }
    }
}

// ---------------- output projection GEMM -------------------------------------
__global__ __launch_bounds__(256, 1)
void gemm_proj(const __nv_bfloat16* __restrict__ Agh, const __nv_bfloat16* __restrict__ Agl,
               const __nv_bfloat16* __restrict__ Bgh, const __nv_bfloat16* __restrict__ Bgl,
               float* __restrict__ C) {
    extern __shared__ __align__(16) char sm[];
    const int m0 = blockIdx.y * GBM, n0 = blockIdx.x * GBN;
    float acc[4][8][4];
    gemm_split_core(Agh + (size_t)m0 * DMODEL, Agl + (size_t)m0 * DMODEL,
                    Bgh + (size_t)n0 * DMODEL, Bgl + (size_t)n0 * DMODEL,
                    DMODEL, DMODEL, DMODEL / GBK, sm, acc);
    const int lane = threadIdx.x & 31, wid = threadIdx.x >> 5;
    const int g = lane >> 2, t = lane & 3;
    const int wm = wid >> 2, wn = wid & 3;
#pragma unroll
    for (int i = 0; i < 4; i++) {
        int m = m0 + wm * 64 + i * 16 + g;
#pragma unroll
        for (int j = 0; j < 8; j++) {
            int n = n0 + wn * 64 + j * 8 + t * 2;
            *(float2*)&C[(size_t)m * DMODEL + n]       = make_float2(acc[i][j][0], acc[i][j][1]);
            *(float2*)&C[(size_t)(m + 8) * DMODEL + n] = make_float2(acc[i][j][2], acc[i][j][3]);
        }
    }
}

// ---------------- fused 4-array fp32 -> bf16 hi/lo split ---------------------
__global__ __launch_bounds__(256)
void conv_split4(const float4* __restrict__ s0, const float4* __restrict__ s1,
                 const float4* __restrict__ s2, const float4* __restrict__ s3,
                 __nv_bfloat162* __restrict__ h0, __nv_bfloat162* __restrict__ l0,
                 __nv_bfloat162* __restrict__ h1, __nv_bfloat162* __restrict__ l1,
                 __nv_bfloat162* __restrict__ h2, __nv_bfloat162* __restrict__ l2,
                 __nv_bfloat162* __restrict__ h3, __nv_bfloat162* __restrict__ l3) {
    int y = blockIdx.y;
    const float4* x = (y == 0) ? s0 : (y == 1) ? s1 : (y == 2) ? s2 : s3;
    __nv_bfloat162* hi = (y == 0) ? h0 : (y == 1) ? h1 : (y == 2) ? h2 : h3;
    __nv_bfloat162* lo = (y == 0) ? l0 : (y == 1) ? l1 : (y == 2) ? l2 : l3;
    int i = blockIdx.x * 256 + threadIdx.x;
    float4 v = x[i];
    __nv_bfloat162 lo0, lo1;
    __nv_bfloat162 hi0 = split_hi2(v.x, v.y, lo0);
    __nv_bfloat162 hi1 = split_hi2(v.z, v.w, lo1);
    hi[2 * i] = hi0; hi[2 * i + 1] = hi1;
    lo[2 * i] = lo0; lo[2 * i + 1] = lo1;
}

__global__ __launch_bounds__(256)
void conv_split_kernel(const float4* __restrict__ x,
                       __nv_bfloat162* __restrict__ hi,
                       __nv_bfloat162* __restrict__ lo) {
    int i = blockIdx.x * 256 + threadIdx.x;
    float4 v = x[i];
    __nv_bfloat162 lo0, lo1;
    __nv_bfloat162 hi0 = split_hi2(v.x, v.y, lo0);
    __nv_bfloat162 hi1 = split_hi2(v.z, v.w, lo1);
    hi[2 * i] = hi0; hi[2 * i + 1] = hi1;
    lo[2 * i] = lo0; lo[2 * i + 1] = lo1;
}

// ---------------- index normalization (all 5 arrays) + inv init --------------
__global__ __launch_bounds__(256)
void conv_idx_all(const unsigned int* __restrict__ p0, const unsigned int* __restrict__ p1,
                  const unsigned int* __restrict__ p2, const unsigned int* __restrict__ p3,
                  const unsigned int* __restrict__ p4,
                  int* __restrict__ out, int* __restrict__ inv_k, int* __restrict__ inv_v) {
    int y = blockIdx.y;
    const unsigned int* raw = (y == 0) ? p0 : (y == 1) ? p1 : (y == 2) ? p2
                              : (y == 3) ? p3 : p4;
    bool is64 = (raw[1] == 0u) && (raw[3] == 0u) && (raw[5] == 0u);
    int i = blockIdx.x * 256 + threadIdx.x;
    out[y * NTOK + i] = is64 ? (int)raw[2 * i] : (int)raw[i];
    if (y == 0) { inv_k[i] = -1; inv_v[i] = -1; }
}

__global__ __launch_bounds__(256)
void scatter_inv(const int* __restrict__ nkl, const int* __restrict__ nvl,
                 int* __restrict__ inv_k, int* __restrict__ inv_v) {
    int t = blockIdx.x * 256 + threadIdx.x;
    inv_k[nkl[t]] = t;
    inv_v[nvl[t]] = t;
}

// ---------------- fused K gather + split (reads K or layer_past) -------------
__global__ __launch_bounds__(256)
void kgather_split(const float4* __restrict__ Kf, const float4* __restrict__ lpk,
                   const int* __restrict__ vki, const int* __restrict__ inv_k,
                   __nv_bfloat162* __restrict__ Kgh,
                   __nv_bfloat162* __restrict__ Kgl) {
    int i = blockIdx.x * 256 + threadIdx.x;       // over NTOK*1024 float4s
    int d4 = i & 63;
    int t  = (i >> 6) & 2047;
    int h  = (i >> 17) & 15;
    int b  = i >> 21;
    int j = vki[b * S_LEN + t];
    int tok = inv_k[j];
    float4 v = (tok >= 0) ? Kf[(size_t)tok * 1024 + h * 64 + d4]
                          : lpk[(size_t)j * 1024 + h * 64 + d4];
    __nv_bfloat162 lo0, lo1;
    __nv_bfloat162 hi0 = split_hi2(v.x, v.y, lo0);
    __nv_bfloat162 hi1 = split_hi2(v.z, v.w, lo1);
    size_t o = (size_t)i * 2;
    Kgh[o] = hi0; Kgh[o + 1] = hi1;
    Kgl[o] = lo0; Kgl[o + 1] = lo1;
}

// ---------------- fused V gather + transpose + split -------------------------
__global__ __launch_bounds__(256)
void vgather_trans_split(const float* __restrict__ Vf, const float* __restrict__ lpv,
                         const int* __restrict__ vvi, const int* __restrict__ inv_v,
                         __nv_bfloat16* __restrict__ Vth,
                         __nv_bfloat16* __restrict__ Vtl) {
    __shared__ float tile[32][33];
    const int bh = blockIdx.z;
    const int b = bh >> 4, h = bh & 15;
    const int s0 = blockIdx.x * 32, d0 = blockIdx.y * 32;
    const int tx = threadIdx.x & 31, ty = threadIdx.x >> 5;
#pragma unroll
    for (int r = 0; r < 32; r += 8) {
        int j = vvi[b * S_LEN + s0 + ty + r];
        int tok = inv_v[j];
        const float* src = (tok >= 0) ? Vf + (size_t)tok * DMODEL
                                      : lpv + (size_t)j * DMODEL;
        tile[ty + r][tx] = src[h * HDIM + d0 + tx];
    }
    __syncthreads();
    __nv_bfloat16* dh = Vth + (size_t)bh * HDIM * S_LEN;
    __nv_bfloat16* dl = Vtl + (size_t)bh * HDIM * S_LEN;
#pragma unroll
    for (int r = 0; r < 32; r += 8) {
        float v = tile[tx][ty + r];
        __nv_bfloat16 hh = __float2bfloat16(v);
        __nv_bfloat16 ll = __float2bfloat16(v - __bfloat162float(hh));
        size_t o = (size_t)(d0 + ty + r) * S_LEN + s0 + tx;
        dh[o] = hh;
        dl[o] = ll;
    }
}

// ---------------- causal row softmax -> bf16 hi/lo prob splits ---------------
__global__ __launch_bounds__(256)
void softmax_split(const float* __restrict__ Sc,
                   __nv_bfloat16* __restrict__ Ph,
                   __nv_bfloat16* __restrict__ Pl) {
    __shared__ float sh[8];
    const int m = blockIdx.x & (S_LEN - 1);       // row within head
    const size_t base = (size_t)blockIdx.x * S_LEN;
    const int iu = m >> 8;                        // highest i with any n<=m
    const int limit = ((m >> 7) + 1) << 7;        // pv reads k in [0, limit)
    const int tid = threadIdx.x;
    const int lane = tid & 31, wid = tid >> 5;
    float v[8];
    float mx = -INFINITY;
#pragma unroll
    for (int i = 0; i < 8; i++) {
        v[i] = -INFINITY;
        if (i <= iu) {
            int n = tid + i * 256;
            v[i] = (n <= m) ? Sc[base + n] : -INFINITY;
            mx = fmaxf(mx, v[i]);
        }
    }
#pragma unroll
    for (int o = 16; o; o >>= 1) mx = fmaxf(mx, __shfl_xor_sync(0xffffffffu, mx, o));
    if (lane == 0) sh[wid] = mx;
    __syncthreads();
    float mall = sh[0];
#pragma unroll
    for (int w = 1; w < 8; w++) mall = fmaxf(mall, sh[w]);
    __syncthreads();
    float s = 0.f;
#pragma unroll
    for (int i = 0; i < 8; i++) {
        if (i <= iu) {
            v[i] = __expf(v[i] - mall);
            s += v[i];
        }
    }
#pragma unroll
    for (int o = 16; o; o >>= 1) s += __shfl_xor_sync(0xffffffffu, s, o);
    if (lane == 0) sh[wid] = s;
    __syncthreads();
    float sall = 0.f;
#pragma unroll
    for (int w = 0; w < 8; w++) sall += sh[w];
    float inv = 1.0f / sall;
#pragma unroll
    for (int i = 0; i < 8; i++) {
        if (i <= iu) {
            int n = tid + i * 256;
            if (n < limit) {
                float p = v[i] * inv;
                __nv_bfloat16 h = __float2bfloat16(p);
                Ph[base + n] = h;
                Pl[base + n] = __float2bfloat16(p - __bfloat162float(h));
            }
        }
    }
}

// ---------------- host launcher ---------------------------------------------
extern "C" void kernel_launch(void* const* d_in, const int* in_sizes, int n_in,
                              void* d_out, int out_size) {
    (void)in_sizes; (void)n_in; (void)out_size;
    const float* hs  = (const float*)d_in[0];
    const float* Wq  = (const float*)d_in[1];
    const float* Wk  = (const float*)d_in[2];
    const float* Wv  = (const float*)d_in[3];
    const float* Wo  = (const float*)d_in[4];
    const float* lpk = (const float*)d_in[5];
    const float* lpv = (const float*)d_in[6];
    const float* am  = (const float*)d_in[7];
    const unsigned int* pos_raw = (const unsigned int*)d_in[8];
    const unsigned int* nkl_raw = (const unsigned int*)d_in[9];
    const unsigned int* nvl_raw = (const unsigned int*)d_in[10];
    const unsigned int* vki_raw = (const unsigned int*)d_in[11];
    const unsigned int* vvi_raw = (const unsigned int*)d_in[12];
    float* out = (float*)d_out;

    float *K, *V, *Sc;
    __nv_bfloat16 *Xh, *Xl, *Qh, *Ql, *Wqh, *Wql, *Wkh, *Wkl, *Wvh, *Wvl, *Woh, *Wol;
    __nv_bfloat16 *Kgh, *Kgl, *Vth, *Vtl, *Ph, *Pl;
    int *idx, *inv;
    cudaGetSymbolAddress((void**)&K,   g_K);
    cudaGetSymbolAddress((void**)&V,   g_V);
    cudaGetSymbolAddress((void**)&Sc,  g_Sc);
    cudaGetSymbolAddress((void**)&idx, g_idx);
    cudaGetSymbolAddress((void**)&inv, g_inv);
    cudaGetSymbolAddress((void**)&Xh,  g_Xh);
    cudaGetSymbolAddress((void**)&Xl,  g_Xl);
    cudaGetSymbolAddress((void**)&Qh,  g_Qh);
    cudaGetSymbolAddress((void**)&Ql,  g_Ql);
    cudaGetSymbolAddress((void**)&Wqh, g_Wqh);
    cudaGetSymbolAddress((void**)&Wql, g_Wql);
    cudaGetSymbolAddress((void**)&Wkh, g_Wkh);
    cudaGetSymbolAddress((void**)&Wkl, g_Wkl);
    cudaGetSymbolAddress((void**)&Wvh, g_Wvh);
    cudaGetSymbolAddress((void**)&Wvl, g_Wvl);
    cudaGetSymbolAddress((void**)&Woh, g_Woh);
    cudaGetSymbolAddress((void**)&Wol, g_Wol);
    cudaGetSymbolAddress((void**)&Kgh, g_Kgh);
    cudaGetSymbolAddress((void**)&Kgl, g_Kgl);
    cudaGetSymbolAddress((void**)&Vth, g_Vth);
    cudaGetSymbolAddress((void**)&Vtl, g_Vtl);
    cudaGetSymbolAddress((void**)&Ph,  g_Ph);
    cudaGetSymbolAddress((void**)&Pl,  g_Pl);
    int* pos = idx + 0 * NTOK;
    int* nkl = idx + 1 * NTOK;
    int* nvl = idx + 2 * NTOK;
    int* vki = idx + 3 * NTOK;
    int* vvi = idx + 4 * NTOK;
    int* inv_k = inv + 0 * NTOK;
    int* inv_v = inv + 1 * NTOK;

    cudaFuncSetAttribute(qkv_mma,   cudaFuncAttributeMaxDynamicSharedMemorySize, GEMM_SMEM);
    cudaFuncSetAttribute(gemm_proj, cudaFuncAttributeMaxDynamicSharedMemorySize, GEMM_SMEM);
    cudaFuncSetAttribute(qk_mma,    cudaFuncAttributeMaxDynamicSharedMemorySize, GEMM_SMEM);
    cudaFuncSetAttribute(pv_mma,    cudaFuncAttributeMaxDynamicSharedMemorySize, GEMM_SMEM);

    const int CONV_BLOCKS = (NTOK * DMODEL / 4) / 256;  // 16384

    // Launch order puts qkv_mma at position 5 so ncu (-s 5 -c 1) profiles it.
    // 1: index normalization (+ inv init)
    conv_idx_all<<<dim3(16, 5), 256>>>(pos_raw, nkl_raw, nvl_raw, vki_raw, vvi_raw,
                                       idx, inv_k, inv_v);
    // 2: inverse cache maps
    scatter_inv<<<16, 256>>>(nkl, nvl, inv_k, inv_v);
    // 3: hs + Wq + Wk + Wv splits (one fused launch)
    conv_split4<<<dim3(CONV_BLOCKS, 4), 256>>>(
        (const float4*)hs, (const float4*)Wq, (const float4*)Wk, (const float4*)Wv,
        (__nv_bfloat162*)Xh,  (__nv_bfloat162*)Xl,
        (__nv_bfloat162*)Wqh, (__nv_bfloat162*)Wql,
        (__nv_bfloat162*)Wkh, (__nv_bfloat162*)Wkl,
        (__nv_bfloat162*)Wvh, (__nv_bfloat162*)Wvl);
    // 4: Wo split
    conv_split_kernel<<<CONV_BLOCKS, 256>>>((const float4*)Wo,
                                            (__nv_bfloat162*)Woh, (__nv_bfloat162*)Wol);
    // 5: fused QKV projection + RoPE  <-- ncu target
    qkv_mma<<<dim3(DMODEL / GBN, DMODEL / GBM, 3), 256, GEMM_SMEM>>>(
        Xh, Xl, Wqh, Wql, Wkh, Wkl, Wvh, Wvl, pos, Qh, Ql, K, V);

    // cache-semantic gathers (inverse-index)
    kgather_split<<<16384, 256>>>((const float4*)K, (const float4*)lpk, vki, inv_k,
                                  (__nv_bfloat162*)Kgh, (__nv_bfloat162*)Kgl);
    vgather_trans_split<<<dim3(S_LEN / 32, HDIM / 32, BH), 256>>>(
        V, lpv, vvi, inv_v, Vth, Vtl);

    // attention
    qk_mma<<<dim3(S_LEN / GBN, S_LEN / GBM, BH), 256, GEMM_SMEM>>>(
        Qh, Ql, Kgh, Kgl, am, Sc);
    softmax_split<<<BH * S_LEN, 256>>>(Sc, Ph, Pl);
    pv_mma<<<dim3(1, S_LEN / GBM, BH), 256, GEMM_SMEM>>>(Ph, Pl, Vth, Vtl, Xh, Xl);

    // output projection
    gemm_proj<<<dim3(DMODEL / GBN, DMODEL / GBM), 256, GEMM_SMEM>>>(
        Xh, Xl, Woh, Wol, out);
}

// round 17
// speedup vs baseline: 1.0014x; 1.0014x over previous
#include <cuda_runtime.h>
#include <cuda_bf16.h>
#include <math.h>
#include <stdint.h>

// Problem constants (fixed by the dataset)
#define S_LEN 2048
#define NHEAD 16
#define HDIM  256
#define BATCH 2
#define DMODEL 4096
#define NTOK  4096              // BATCH * S_LEN
#define BH    32                // BATCH * NHEAD

// ---------------- scratch (device globals; no allocations allowed) ----------
__device__ float g_K [(size_t)NTOK * DMODEL];   // post-RoPE K (fp32, cache source)
__device__ float g_V [(size_t)NTOK * DMODEL];
__device__ float g_Sc[(size_t)BH * S_LEN * S_LEN]; // fp32 scores
__device__ int   g_idx[5][NTOK];
__device__ int   g_inv[2][NTOK];                // inverse cache maps (k, v)
// bf16 split buffers
__device__ __nv_bfloat16 g_Xh[(size_t)NTOK * DMODEL];   // hs splits, later O splits
__device__ __nv_bfloat16 g_Xl[(size_t)NTOK * DMODEL];
__device__ __nv_bfloat16 g_Qh[(size_t)NTOK * DMODEL];   // post-RoPE Q splits
__device__ __nv_bfloat16 g_Ql[(size_t)NTOK * DMODEL];
__device__ __nv_bfloat16 g_Wqh[(size_t)DMODEL * DMODEL];
__device__ __nv_bfloat16 g_Wql[(size_t)DMODEL * DMODEL];
__device__ __nv_bfloat16 g_Wkh[(size_t)DMODEL * DMODEL];
__device__ __nv_bfloat16 g_Wkl[(size_t)DMODEL * DMODEL];
__device__ __nv_bfloat16 g_Wvh[(size_t)DMODEL * DMODEL];
__device__ __nv_bfloat16 g_Wvl[(size_t)DMODEL * DMODEL];
__device__ __nv_bfloat16 g_Woh[(size_t)DMODEL * DMODEL];
__device__ __nv_bfloat16 g_Wol[(size_t)DMODEL * DMODEL];
__device__ __nv_bfloat16 g_Kgh[(size_t)NTOK * DMODEL];  // gathered K split [BH][S][HD]
__device__ __nv_bfloat16 g_Kgl[(size_t)NTOK * DMODEL];
__device__ __nv_bfloat16 g_Vth[(size_t)NTOK * DMODEL];  // V^T split: [BH][HD][S]
__device__ __nv_bfloat16 g_Vtl[(size_t)NTOK * DMODEL];
__device__ __nv_bfloat16 g_Ph[(size_t)BH * S_LEN * S_LEN];  // prob split
__device__ __nv_bfloat16 g_Pl[(size_t)BH * S_LEN * S_LEN];

// ============================================================================
// helpers
// ============================================================================
__device__ __forceinline__ uint32_t smem_u32(const void* p) {
    uint32_t a;
    asm("{ .reg .u64 t; cvta.to.shared.u64 t, %1; cvt.u32.u64 %0, t; }"
        : "=r"(a) : "l"(p));
    return a;
}
__device__ __forceinline__ void cp_async16(uint32_t dst, const void* src) {
    asm volatile("cp.async.cg.shared.global [%0], [%1], 16;"
                 :: "r"(dst), "l"(src) : "memory");
}
__device__ __forceinline__ void cp_commit() {
    asm volatile("cp.async.commit_group;" ::: "memory");
}
__device__ __forceinline__ void cp_wait1() {
    asm volatile("cp.async.wait_group 1;" ::: "memory");
}
__device__ __forceinline__ void mma_bf16(float* d, const uint32_t* a, const uint32_t* b) {
    asm volatile(
        "mma.sync.aligned.m16n8k16.row.col.f32.bf16.bf16.f32 "
        "{%0,%1,%2,%3}, {%4,%5,%6,%7}, {%8,%9}, {%0,%1,%2,%3};"
        : "+f"(d[0]), "+f"(d[1]), "+f"(d[2]), "+f"(d[3])
        : "r"(a[0]), "r"(a[1]), "r"(a[2]), "r"(a[3]), "r"(b[0]), "r"(b[1]));
}
__device__ __forceinline__ void ldsm_x4(uint32_t* r, uint32_t addr) {
    asm volatile("ldmatrix.sync.aligned.m8n8.x4.shared.b16 {%0,%1,%2,%3}, [%4];"
                 : "=r"(r[0]), "=r"(r[1]), "=r"(r[2]), "=r"(r[3]) : "r"(addr));
}
__device__ __forceinline__ __nv_bfloat162 split_hi2(float a, float b,
                                                    __nv_bfloat162& lo) {
    __nv_bfloat16 h0 = __float2bfloat16(a);
    __nv_bfloat16 h1 = __float2bfloat16(b);
    lo = __halves2bfloat162(__float2bfloat16(a - __bfloat162float(h0)),
                            __float2bfloat16(b - __bfloat162float(h1)));
    return __halves2bfloat162(h0, h1);
}

// ============================================================================
// shared bf16-split mma core: CTA tile 128(M) x 256(N) x 32(K), 8 warps (2x4),
// warp tile 64x64, 3-stage cp.async pipeline, 80B-padded smem rows.
// acc = Ah*Bh^T + Ah*Bl^T + Al*Bh^T over kiters*32 K elements.
// Fragment loads via ldmatrix.x4 (16 per k16 slice instead of 64 LDS.32).
// ============================================================================
#define GBM 128
#define GBN 256
#define GBK 32
#define ROWB 80
#define SM_A_SZ (GBM * ROWB)            // 10240
#define SM_B_SZ (GBN * ROWB)            // 20480
#define OFF_AH 0
#define OFF_AL SM_A_SZ
#define OFF_BH (2 * SM_A_SZ)
#define OFF_BL (2 * SM_A_SZ + SM_B_SZ)
#define STAGE_B (2 * SM_A_SZ + 2 * SM_B_SZ)  // 61440
#define PIPE 3
#define GEMM_SMEM (PIPE * STAGE_B)      // 184320

__device__ __forceinline__ void gemm_split_core(
    const __nv_bfloat16* __restrict__ Ah, const __nv_bfloat16* __restrict__ Al,
    const __nv_bfloat16* __restrict__ Bh, const __nv_bfloat16* __restrict__ Bl,
    int64_t lda, int64_t ldb, int kiters,
    char* sm, float acc[4][8][4])
{
    const uint32_t sbase = smem_u32(sm);
    const int tid  = threadIdx.x;
    const int lane = tid & 31;
    const int wid = tid >> 5;
    const int wm = wid >> 2, wn = wid & 3;

#pragma unroll
    for (int i = 0; i < 4; i++)
#pragma unroll
        for (int j = 0; j < 8; j++)
#pragma unroll
            for (int r = 0; r < 4; r++) acc[i][j][r] = 0.f;

    // ---- compressed cp.async addressing: 4 base pointers + strides ----
    const int arow = tid >> 2, akc = tid & 3;
    const __nv_bfloat16* srcAh = Ah + (int64_t)arow * lda + akc * 8;
    const __nv_bfloat16* srcAl = Al + (int64_t)arow * lda + akc * 8;
    const __nv_bfloat16* srcBh = Bh + (int64_t)arow * ldb + akc * 8;
    const __nv_bfloat16* srcBl = Bl + (int64_t)arow * ldb + akc * 8;
    const int64_t sa = 64 * lda;
    const int64_t sb = 64 * ldb;
    const uint32_t dbase = (uint32_t)(arow * ROWB + akc * 16);

    auto issue = [&](int s) {
        uint32_t dA = sbase + s * STAGE_B + dbase;
        cp_async16(dA + OFF_AH,             srcAh);
        cp_async16(dA + OFF_AH + 64 * ROWB, srcAh + sa);
        cp_async16(dA + OFF_AL,             srcAl);
        cp_async16(dA + OFF_AL + 64 * ROWB, srcAl + sa);
#pragma unroll
        for (int r = 0; r < 4; r++) {
            cp_async16(dA + OFF_BH + r * 64 * ROWB, srcBh + r * sb);
            cp_async16(dA + OFF_BL + r * 64 * ROWB, srcBl + r * sb);
        }
        srcAh += GBK; srcAl += GBK; srcBh += GBK; srcBl += GBK;
    };

    issue(0); cp_commit();
    issue(1); cp_commit();

    // ---- ldmatrix per-lane base offsets (within a stage) ----
    const int sub = lane >> 3;            // 0..3 (matrix id within x4)
    const int lr8 = lane & 7;
    const uint32_t a_off = (uint32_t)((wm * 64 + (sub & 1) * 8 + lr8) * ROWB
                                      + (sub >> 1) * 16);
    const uint32_t b_off = (uint32_t)((wn * 64 + (sub & 1) * 8 + lr8) * ROWB
                                      + (sub >> 1) * 16);

    for (int it = 0; it < kiters; it++) {
        cp_wait1();
        __syncthreads();
        const uint32_t stg = sbase + (it % PIPE) * STAGE_B;

#pragma unroll
        for (int ks = 0; ks < 2; ks++) {
            const uint32_t ka = stg + ks * 32;
            uint32_t ah[4][4], al[4][4], bh2[4][4], bl2[4][4];
#pragma unroll
            for (int i = 0; i < 4; i++)
                ldsm_x4(ah[i], ka + OFF_AH + a_off + i * (16 * ROWB));
#pragma unroll
            for (int jp = 0; jp < 4; jp++)
                ldsm_x4(bh2[jp], ka + OFF_BH + b_off + jp * (16 * ROWB));
            // bh2[jp] = {b(2jp)[0], b(2jp+1)[0], b(2jp)[1], b(2jp+1)[1]}
#pragma unroll
            for (int jp = 0; jp < 4; jp++) {
                uint32_t b0[2] = {bh2[jp][0], bh2[jp][2]};
                uint32_t b1[2] = {bh2[jp][1], bh2[jp][3]};
#pragma unroll
                for (int i = 0; i < 4; i++) {
                    mma_bf16(acc[i][2 * jp],     ah[i], b0);
                    mma_bf16(acc[i][2 * jp + 1], ah[i], b1);
                }
            }

#pragma unroll
            for (int jp = 0; jp < 4; jp++)
                ldsm_x4(bl2[jp], ka + OFF_BL + b_off + jp * (16 * ROWB));
#pragma unroll
            for (int jp = 0; jp < 4; jp++) {
                uint32_t b0[2] = {bl2[jp][0], bl2[jp][2]};
                uint32_t b1[2] = {bl2[jp][1], bl2[jp][3]};
#pragma unroll
                for (int i = 0; i < 4; i++) {
                    mma_bf16(acc[i][2 * jp],     ah[i], b0);
                    mma_bf16(acc[i][2 * jp + 1], ah[i], b1);
                }
            }

#pragma unroll
            for (int i = 0; i < 4; i++)
                ldsm_x4(al[i], ka + OFF_AL + a_off + i * (16 * ROWB));
#pragma unroll
            for (int jp = 0; jp < 4; jp++) {
                uint32_t b0[2] = {bh2[jp][0], bh2[jp][2]};
                uint32_t b1[2] = {bh2[jp][1], bh2[jp][3]};
#pragma unroll
                for (int i = 0; i < 4; i++) {
                    mma_bf16(acc[i][2 * jp],     al[i], b0);
                    mma_bf16(acc[i][2 * jp + 1], al[i], b1);
                }
            }
        }

        if (it + 2 < kiters) issue((it + 2) % PIPE);
        cp_commit();
    }
}

// ---------------- fused QKV projection GEMM + RoPE epilogue ------------------
// z=0: Q -> RoPE -> bf16 splits; z=1: K -> RoPE -> fp32; z=2: V -> fp32.
__global__ __launch_bounds__(256, 1)
void qkv_mma(const __nv_bfloat16* __restrict__ Xh, const __nv_bfloat16* __restrict__ Xl,
             const __nv_bfloat16* __restrict__ Wqh, const __nv_bfloat16* __restrict__ Wql,
             const __nv_bfloat16* __restrict__ Wkh, const __nv_bfloat16* __restrict__ Wkl,
             const __nv_bfloat16* __restrict__ Wvh, const __nv_bfloat16* __restrict__ Wvl,
             const int* __restrict__ pos_ids,
             __nv_bfloat16* __restrict__ Qh, __nv_bfloat16* __restrict__ Ql,
             float* __restrict__ K, float* __restrict__ V) {
    extern __shared__ __align__(16) char sm[];
    const int z = blockIdx.z;
    const int m0 = blockIdx.y * GBM, n0 = blockIdx.x * GBN;
    const __nv_bfloat16* Bh = (z == 0) ? Wqh : (z == 1) ? Wkh : Wvh;
    const __nv_bfloat16* Bl = (z == 0) ? Wql : (z == 1) ? Wkl : Wvl;
    float acc[4][8][4];
    gemm_split_core(Xh + (size_t)m0 * DMODEL, Xl + (size_t)m0 * DMODEL,
                    Bh + (size_t)n0 * DMODEL, Bl + (size_t)n0 * DMODEL,
                    DMODEL, DMODEL, DMODEL / GBK, sm, acc);

    const int lane = threadIdx.x & 31, wid = threadIdx.x >> 5;
    const int g = lane >> 2, t = lane & 3;
    const int wm = wid >> 2, wn = wid & 3;
    const bool do_rope = (z < 2) && (wn == 0);   // head-local cols 0..62

#pragma unroll
    for (int i = 0; i < 4; i++) {
        int m = m0 + wm * 64 + i * 16 + g;       // global token index
        float p0 = 0.f, p1 = 0.f;
        if (do_rope) {
            p0 = (float)pos_ids[m];
            p1 = (float)pos_ids[m + 8];
        }
#pragma unroll
        for (int j = 0; j < 8; j++) {
            int n = n0 + wn * 64 + j * 8 + t * 2;
            float v0 = acc[i][j][0], v1 = acc[i][j][1];
            float v2 = acc[i][j][2], v3 = acc[i][j][3];
            if (do_rope) {
                int f = j * 4 + t;
                // 10000^(-2f/64) = exp(-f * ln(10000)/32)
                float ivf = __expf(-0.28782313662425572f * (float)f);
                float s0, c0, s1, c1;
                __sincosf(p0 * ivf, &s0, &c0);
                __sincosf(p1 * ivf, &s1, &c1);
                float nv0 = c0 * v0 - s0 * v1, nv1 = s0 * v0 + c0 * v1;
                float nv2 = c1 * v2 - s1 * v3, nv3 = s1 * v2 + c1 * v3;
                v0 = nv0; v1 = nv1; v2 = nv2; v3 = nv3;
            }
            if (z == 0) {
                __nv_bfloat162 lo0, lo1;
                __nv_bfloat162 hi0 = split_hi2(v0, v1, lo0);
                __nv_bfloat162 hi1 = split_hi2(v2, v3, lo1);
                *(__nv_bfloat162*)&Qh[(size_t)m * DMODEL + n]       = hi0;
                *(__nv_bfloat162*)&Ql[(size_t)m * DMODEL + n]       = lo0;
                *(__nv_bfloat162*)&Qh[(size_t)(m + 8) * DMODEL + n] = hi1;
                *(__nv_bfloat162*)&Ql[(size_t)(m + 8) * DMODEL + n] = lo1;
            } else {
                float* C = (z == 1) ? K : V;
                *(float2*)&C[(size_t)m * DMODEL + n]       = make_float2(v0, v1);
                *(float2*)&C[(size_t)(m + 8) * DMODEL + n] = make_float2(v2, v3);
            }
        }
    }
}

// ---------------- QK^T GEMM: causal mask + scale + attention mask -----------
__global__ __launch_bounds__(256, 1)
void qk_mma(const __nv_bfloat16* __restrict__ Qh, const __nv_bfloat16* __restrict__ Ql,
            const __nv_bfloat16* __restrict__ Kh, const __nv_bfloat16* __restrict__ Kl,
            const float* __restrict__ am, float* __restrict__ Sc) {
    extern __shared__ __align__(16) char sm[];
    const int bh = blockIdx.z;
    const int b = bh >> 4, h = bh & 15;
    const int m0 = blockIdx.y * GBM, n0 = blockIdx.x * GBN;
    if (n0 > m0 + (GBM - 1)) return;   // fully masked: softmax never reads it

    float* Cb = Sc + (size_t)bh * S_LEN * S_LEN;
    const size_t aoff = (size_t)b * S_LEN * DMODEL + (size_t)h * HDIM + (size_t)m0 * DMODEL;
    const size_t boff = (size_t)bh * S_LEN * HDIM + (size_t)n0 * HDIM;
    float acc[4][8][4];
    gemm_split_core(Qh + aoff, Ql + aoff, Kh + boff, Kl + boff,
                    DMODEL, HDIM, HDIM / GBK, sm, acc);

    const int lane = threadIdx.x & 31, wid = threadIdx.x >> 5;
    const int g = lane >> 2, t = lane & 3;
    const int wm = wid >> 2, wn = wid & 3;
    const float scale = 1.0f / 16.0f;
#pragma unroll
    for (int i = 0; i < 4; i++) {
        int m = m0 + wm * 64 + i * 16 + g;
#pragma unroll
        for (int j = 0; j < 8; j++) {
            int n = n0 + wn * 64 + j * 8 + t * 2;
            float amv0 = am[b * S_LEN + n], amv1 = am[b * S_LEN + n + 1];
            float v0 = (n     <= m) ? (acc[i][j][0] * scale + amv0) : -1e30f;
            float v1 = (n + 1 <= m) ? (acc[i][j][1] * scale + amv1) : -1e30f;
            float v2 = (n     <= m + 8) ? (acc[i][j][2] * scale + amv0) : -1e30f;
            float v3 = (n + 1 <= m + 8) ? (acc[i][j][3] * scale + amv1) : -1e30f;
            *(float2*)&Cb[(size_t)m * S_LEN + n]       = make_float2(v0, v1);
            *(float2*)&Cb[(size_t)(m + 8) * S_LEN + n] = make_float2(v2, v3);
        }
    }
}

// ---------------- PV GEMM -> bf16 split O epilogue ---------------------------
__global__ __launch_bounds__(256, 1)
void pv_mma(const __nv_bfloat16* __restrict__ Ph, const __nv_bfloat16* __restrict__ Pl,
            const __nv_bfloat16* __restrict__ Vth, const __nv_bfloat16* __restrict__ Vtl,
            __nv_bfloat16* __restrict__ Oh, __nv_bfloat16* __restrict__ Ol) {
    extern __shared__ __align__(16) char sm[];
    const int bh = blockIdx.z;
    const int b = bh >> 4, h = bh & 15;
    // reversed order: longest-running tiles (largest m0) launch first
    const int m0 = (gridDim.y - 1 - blockIdx.y) * GBM;
    const size_t aoff = (size_t)bh * S_LEN * S_LEN + (size_t)m0 * S_LEN;
    const size_t boff = (size_t)bh * HDIM * S_LEN;
    float acc[4][8][4];
    gemm_split_core(Ph + aoff, Pl + aoff, Vth + boff, Vtl + boff,
                    S_LEN, S_LEN, (m0 + GBM) / GBK, sm, acc);

    const int lane = threadIdx.x & 31, wid = threadIdx.x >> 5;
    const int g = lane >> 2, t = lane & 3;
    const int wm = wid >> 2, wn = wid & 3;
#pragma unroll
    for (int i = 0; i < 4; i++) {
        int m = m0 + wm * 64 + i * 16 + g;
        size_t tok0 = (size_t)b * S_LEN + m;
#pragma unroll
        for (int j = 0; j < 8; j++) {
            int n = wn * 64 + j * 8 + t * 2;
            __nv_bfloat162 lo0, lo1;
            __nv_bfloat162 hi0 = split_hi2(acc[i][j][0], acc[i][j][1], lo0);
            __nv_bfloat162 hi1 = split_hi2(acc[i][j][2], acc[i][j][3], lo1);
            *(__nv_bfloat162*)&Oh[tok0 * DMODEL + h * HDIM + n]       = hi0;
            *(__nv_bfloat162*)&Ol[tok0 * DMODEL + h * HDIM + n]       = lo0;
            *(__nv_bfloat162*)&Oh[(tok0 + 8) * DMODEL + h * HDIM + n] = hi1;
            *(__nv_bfloat162*)&Ol[(tok0 + 8) * DMODEL + h * HDIM + n] = lo1;
        }
    }
}

// ---------------- output projection GEMM -------------------------------------
__global__ __launch_bounds__(256, 1)
void gemm_proj(const __nv_bfloat16* __restrict__ Agh, const __nv_bfloat16* __restrict__ Agl,
               const __nv_bfloat16* __restrict__ Bgh, const __nv_bfloat16* __restrict__ Bgl,
               float* __restrict__ C) {
    extern __shared__ __align__(16) char sm[];
    const int m0 = blockIdx.y * GBM, n0 = blockIdx.x * GBN;
    float acc[4][8][4];
    gemm_split_core(Agh + (size_t)m0 * DMODEL, Agl + (size_t)m0 * DMODEL,
                    Bgh + (size_t)n0 * DMODEL, Bgl + (size_t)n0 * DMODEL,
                    DMODEL, DMODEL, DMODEL / GBK, sm, acc);
    const int lane = threadIdx.x & 31, wid = threadIdx.x >> 5;
    const int g = lane >> 2, t = lane & 3;
    const int wm = wid >> 2, wn = wid & 3;
#pragma unroll
    for (int i = 0; i < 4; i++) {
        int m = m0 + wm * 64 + i * 16 + g;
#pragma unroll
        for (int j = 0; j < 8; j++) {
            int n = n0 + wn * 64 + j * 8 + t * 2;
            *(float2*)&C[(size_t)m * DMODEL + n]       = make_float2(acc[i][j][0], acc[i][j][1]);
            *(float2*)&C[(size_t)(m + 8) * DMODEL + n] = make_float2(acc[i][j][2], acc[i][j][3]);
        }
    }
}

// ---------------- fused 4-array fp32 -> bf16 hi/lo split ---------------------
__global__ __launch_bounds__(256)
void conv_split4(const float4* __restrict__ s0, const float4* __restrict__ s1,
                 const float4* __restrict__ s2, const float4* __restrict__ s3,
                 __nv_bfloat162* __restrict__ h0, __nv_bfloat162* __restrict__ l0,
                 __nv_bfloat162* __restrict__ h1, __nv_bfloat162* __restrict__ l1,
                 __nv_bfloat162* __restrict__ h2, __nv_bfloat162* __restrict__ l2,
                 __nv_bfloat162* __restrict__ h3, __nv_bfloat162* __restrict__ l3) {
    int y = blockIdx.y;
    const float4* x = (y == 0) ? s0 : (y == 1) ? s1 : (y == 2) ? s2 : s3;
    __nv_bfloat162* hi = (y == 0) ? h0 : (y == 1) ? h1 : (y == 2) ? h2 : h3;
    __nv_bfloat162* lo = (y == 0) ? l0 : (y == 1) ? l1 : (y == 2) ? l2 : l3;
    int i = blockIdx.x * 256 + threadIdx.x;
    float4 v = x[i];
    __nv_bfloat162 lo0, lo1;
    __nv_bfloat162 hi0 = split_hi2(v.x, v.y, lo0);
    __nv_bfloat162 hi1 = split_hi2(v.z, v.w, lo1);
    hi[2 * i] = hi0; hi[2 * i + 1] = hi1;
    lo[2 * i] = lo0; lo[2 * i + 1] = lo1;
}

__global__ __launch_bounds__(256)
void conv_split_kernel(const float4* __restrict__ x,
                       __nv_bfloat162* __restrict__ hi,
                       __nv_bfloat162* __restrict__ lo) {
    int i = blockIdx.x * 256 + threadIdx.x;
    float4 v = x[i];
    __nv_bfloat162 lo0, lo1;
    __nv_bfloat162 hi0 = split_hi2(v.x, v.y, lo0);
    __nv_bfloat162 hi1 = split_hi2(v.z, v.w, lo1);
    hi[2 * i] = hi0; hi[2 * i + 1] = hi1;
    lo[2 * i] = lo0; lo[2 * i + 1] = lo1;
}

// ---------------- index normalization (all 5 arrays) + inv init --------------
__global__ __launch_bounds__(256)
void conv_idx_all(const unsigned int* __restrict__ p0, const unsigned int* __restrict__ p1,
                  const unsigned int* __restrict__ p2, const unsigned int* __restrict__ p3,
                  const unsigned int* __restrict__ p4,
                  int* __restrict__ out, int* __restrict__ inv_k, int* __restrict__ inv_v) {
    int y = blockIdx.y;
    const unsigned int* raw = (y == 0) ? p0 : (y == 1) ? p1 : (y == 2) ? p2
                              : (y == 3) ? p3 : p4;
    bool is64 = (raw[1] == 0u) && (raw[3] == 0u) && (raw[5] == 0u);
    int i = blockIdx.x * 256 + threadIdx.x;
    out[y * NTOK + i] = is64 ? (int)raw[2 * i] : (int)raw[i];
    if (y == 0) { inv_k[i] = -1; inv_v[i] = -1; }
}

__global__ __launch_bounds__(256)
void scatter_inv(const int* __restrict__ nkl, const int* __restrict__ nvl,
                 int* __restrict__ inv_k, int* __restrict__ inv_v) {
    int t = blockIdx.x * 256 + threadIdx.x;
    inv_k[nkl[t]] = t;
    inv_v[nvl[t]] = t;
}

// ---------------- fused K gather + split (reads K or layer_past) -------------
__global__ __launch_bounds__(256)
void kgather_split(const float4* __restrict__ Kf, const float4* __restrict__ lpk,
                   const int* __restrict__ vki, const int* __restrict__ inv_k,
                   __nv_bfloat162* __restrict__ Kgh,
                   __nv_bfloat162* __restrict__ Kgl) {
    int i = blockIdx.x * 256 + threadIdx.x;       // over NTOK*1024 float4s
    int d4 = i & 63;
    int t  = (i >> 6) & 2047;
    int h  = (i >> 17) & 15;
    int b  = i >> 21;
    int j = vki[b * S_LEN + t];
    int tok = inv_k[j];
    float4 v = (tok >= 0) ? Kf[(size_t)tok * 1024 + h * 64 + d4]
                          : lpk[(size_t)j * 1024 + h * 64 + d4];
    __nv_bfloat162 lo0, lo1;
    __nv_bfloat162 hi0 = split_hi2(v.x, v.y, lo0);
    __nv_bfloat162 hi1 = split_hi2(v.z, v.w, lo1);
    size_t o = (size_t)i * 2;
    Kgh[o] = hi0; Kgh[o + 1] = hi1;
    Kgl[o] = lo0; Kgl[o + 1] = lo1;
}

// ---------------- fused V gather + transpose + split -------------------------
__global__ __launch_bounds__(256)
void vgather_trans_split(const float* __restrict__ Vf, const float* __restrict__ lpv,
                         const int* __restrict__ vvi, const int* __restrict__ inv_v,
                         __nv_bfloat16* __restrict__ Vth,
                         __nv_bfloat16* __restrict__ Vtl) {
    __shared__ float tile[32][33];
    const int bh = blockIdx.z;
    const int b = bh >> 4, h = bh & 15;
    const int s0 = blockIdx.x * 32, d0 = blockIdx.y * 32;
    const int tx = threadIdx.x & 31, ty = threadIdx.x >> 5;
#pragma unroll
    for (int r = 0; r < 32; r += 8) {
        int j = vvi[b * S_LEN + s0 + ty + r];
        int tok = inv_v[j];
        const float* src = (tok >= 0) ? Vf + (size_t)tok * DMODEL
                                      : lpv + (size_t)j * DMODEL;
        tile[ty + r][tx] = src[h * HDIM + d0 + tx];
    }
    __syncthreads();
    __nv_bfloat16* dh = Vth + (size_t)bh * HDIM * S_LEN;
    __nv_bfloat16* dl = Vtl + (size_t)bh * HDIM * S_LEN;
#pragma unroll
    for (int r = 0; r < 32; r += 8) {
        float v = tile[tx][ty + r];
        __nv_bfloat16 hh = __float2bfloat16(v);
        __nv_bfloat16 ll = __float2bfloat16(v - __bfloat162float(hh));
        size_t o = (size_t)(d0 + ty + r) * S_LEN + s0 + tx;
        dh[o] = hh;
        dl[o] = ll;
    }
}

// ---------------- causal row softmax -> bf16 hi/lo prob splits ---------------
__global__ __launch_bounds__(256)
void softmax_split(const float* __restrict__ Sc,
                   __nv_bfloat16* __restrict__ Ph,
                   __nv_bfloat16* __restrict__ Pl) {
    __shared__ float sh[8];
    const int m = blockIdx.x & (S_LEN - 1);       // row within head
    const size_t base = (size_t)blockIdx.x * S_LEN;
    const int iu = m >> 8;                        // highest i with any n<=m
    const int limit = ((m >> 7) + 1) << 7;        // pv reads k in [0, limit)
    const int tid = threadIdx.x;
    const int lane = tid & 31, wid = tid >> 5;
    float v[8];
    float mx = -INFINITY;
#pragma unroll
    for (int i = 0; i < 8; i++) {
        v[i] = -INFINITY;
        if (i <= iu) {
            int n = tid + i * 256;
            v[i] = (n <= m) ? Sc[base + n] : -INFINITY;
            mx = fmaxf(mx, v[i]);
        }
    }
#pragma unroll
    for (int o = 16; o; o >>= 1) mx = fmaxf(mx, __shfl_xor_sync(0xffffffffu, mx, o));
    if (lane == 0) sh[wid] = mx;
    __syncthreads();
    float mall = sh[0];
#pragma unroll
    for (int w = 1; w < 8; w++) mall = fmaxf(mall, sh[w]);
    __syncthreads();
    float s = 0.f;
#pragma unroll
    for (int i = 0; i < 8; i++) {
        if (i <= iu) {
            v[i] = __expf(v[i] - mall);
            s += v[i];
        }
    }
#pragma unroll
    for (int o = 16; o; o >>= 1) s += __shfl_xor_sync(0xffffffffu, s, o);
    if (lane == 0) sh[wid] = s;
    __syncthreads();
    float sall = 0.f;
#pragma unroll
    for (int w = 0; w < 8; w++) sall += sh[w];
    float inv = 1.0f / sall;
#pragma unroll
    for (int i = 0; i < 8; i++) {
        if (i <= iu) {
            int n = tid + i * 256;
            if (n < limit) {
                float p = v[i] * inv;
                __nv_bfloat16 h = __float2bfloat16(p);
                Ph[base + n] = h;
                Pl[base + n] = __float2bfloat16(p - __bfloat162float(h));
            }
        }
    }
}

// ---------------- host launcher ---------------------------------------------
extern "C" void kernel_launch(void* const* d_in, const int* in_sizes, int n_in,
                              void* d_out, int out_size) {
    (void)in_sizes; (void)n_in; (void)out_size;
    const float* hs  = (const float*)d_in[0];
    const float* Wq  = (const float*)d_in[1];
    const float* Wk  = (const float*)d_in[2];
    const float* Wv  = (const float*)d_in[3];
    const float* Wo  = (const float*)d_in[4];
    const float* lpk = (const float*)d_in[5];
    const float* lpv = (const float*)d_in[6];
    const float* am  = (const float*)d_in[7];
    const unsigned int* pos_raw = (const unsigned int*)d_in[8];
    const unsigned int* nkl_raw = (const unsigned int*)d_in[9];
    const unsigned int* nvl_raw = (const unsigned int*)d_in[10];
    const unsigned int* vki_raw = (const unsigned int*)d_in[11];
    const unsigned int* vvi_raw = (const unsigned int*)d_in[12];
    float* out = (float*)d_out;

    float *K, *V, *Sc;
    __nv_bfloat16 *Xh, *Xl, *Qh, *Ql, *Wqh, *Wql, *Wkh, *Wkl, *Wvh, *Wvl, *Woh, *Wol;
    __nv_bfloat16 *Kgh, *Kgl, *Vth, *Vtl, *Ph, *Pl;
    int *idx, *inv;
    cudaGetSymbolAddress((void**)&K,   g_K);
    cudaGetSymbolAddress((void**)&V,   g_V);
    cudaGetSymbolAddress((void**)&Sc,  g_Sc);
    cudaGetSymbolAddress((void**)&idx, g_idx);
    cudaGetSymbolAddress((void**)&inv, g_inv);
    cudaGetSymbolAddress((void**)&Xh,  g_Xh);
    cudaGetSymbolAddress((void**)&Xl,  g_Xl);
    cudaGetSymbolAddress((void**)&Qh,  g_Qh);
    cudaGetSymbolAddress((void**)&Ql,  g_Ql);
    cudaGetSymbolAddress((void**)&Wqh, g_Wqh);
    cudaGetSymbolAddress((void**)&Wql, g_Wql);
    cudaGetSymbolAddress((void**)&Wkh, g_Wkh);
    cudaGetSymbolAddress((void**)&Wkl, g_Wkl);
    cudaGetSymbolAddress((void**)&Wvh, g_Wvh);
    cudaGetSymbolAddress((void**)&Wvl, g_Wvl);
    cudaGetSymbolAddress((void**)&Woh, g_Woh);
    cudaGetSymbolAddress((void**)&Wol, g_Wol);
    cudaGetSymbolAddress((void**)&Kgh, g_Kgh);
    cudaGetSymbolAddress((void**)&Kgl, g_Kgl);
    cudaGetSymbolAddress((void**)&Vth, g_Vth);
    cudaGetSymbolAddress((void**)&Vtl, g_Vtl);
    cudaGetSymbolAddress((void**)&Ph,  g_Ph);
    cudaGetSymbolAddress((void**)&Pl,  g_Pl);
    int* pos = idx + 0 * NTOK;
    int* nkl = idx + 1 * NTOK;
    int* nvl = idx + 2 * NTOK;
    int* vki = idx + 3 * NTOK;
    int* vvi = idx + 4 * NTOK;
    int* inv_k = inv + 0 * NTOK;
    int* inv_v = inv + 1 * NTOK;

    cudaFuncSetAttribute(qkv_mma,   cudaFuncAttributeMaxDynamicSharedMemorySize, GEMM_SMEM);
    cudaFuncSetAttribute(gemm_proj, cudaFuncAttributeMaxDynamicSharedMemorySize, GEMM_SMEM);
    cudaFuncSetAttribute(qk_mma,    cudaFuncAttributeMaxDynamicSharedMemorySize, GEMM_SMEM);
    cudaFuncSetAttribute(pv_mma,    cudaFuncAttributeMaxDynamicSharedMemorySize, GEMM_SMEM);

    const int CONV_BLOCKS = (NTOK * DMODEL / 4) / 256;  // 16384

    // Launch order puts qkv_mma at position 5 so ncu (-s 5 -c 1) profiles it.
    // 1: index normalization (+ inv init)
    conv_idx_all<<<dim3(16, 5), 256>>>(pos_raw, nkl_raw, nvl_raw, vki_raw, vvi_raw,
                                       idx, inv_k, inv_v);
    // 2: inverse cache maps
    scatter_inv<<<16, 256>>>(nkl, nvl, inv_k, inv_v);
    // 3: hs + Wq + Wk + Wv splits (one fused launch)
    conv_split4<<<dim3(CONV_BLOCKS, 4), 256>>>(
        (const float4*)hs, (const float4*)Wq, (const float4*)Wk, (const float4*)Wv,
        (__nv_bfloat162*)Xh,  (__nv_bfloat162*)Xl,
        (__nv_bfloat162*)Wqh, (__nv_bfloat162*)Wql,
        (__nv_bfloat162*)Wkh, (__nv_bfloat162*)Wkl,
        (__nv_bfloat162*)Wvh, (__nv_bfloat162*)Wvl);
    // 4: Wo split
    conv_split_kernel<<<CONV_BLOCKS, 256>>>((const float4*)Wo,
                                            (__nv_bfloat162*)Woh, (__nv_bfloat162*)Wol);
    // 5: fused QKV projection + RoPE  <-- ncu target
    qkv_mma<<<dim3(DMODEL / GBN, DMODEL / GBM, 3), 256, GEMM_SMEM>>>(
        Xh, Xl, Wqh, Wql, Wkh, Wkl, Wvh, Wvl, pos, Qh, Ql, K, V);

    // cache-semantic gathers (inverse-index)
    kgather_split<<<16384, 256>>>((const float4*)K, (const float4*)lpk, vki, inv_k,
                                  (__nv_bfloat162*)Kgh, (__nv_bfloat162*)Kgl);
    vgather_trans_split<<<dim3(S_LEN / 32, HDIM / 32, BH), 256>>>(
        V, lpv, vvi, inv_v, Vth, Vtl);

    // attention
    qk_mma<<<dim3(S_LEN / GBN, S_LEN / GBM, BH), 256, GEMM_SMEM>>>(
        Qh, Ql, Kgh, Kgl, am, Sc);
    softmax_split<<<BH * S_LEN, 256>>>(Sc, Ph, Pl);
    pv_mma<<<dim3(1, S_LEN / GBM, BH), 256, GEMM_SMEM>>>(Ph, Pl, Vth, Vtl, Xh, Xl);

    // output projection
    gemm_proj<<<dim3(DMODEL / GBN, DMODEL / GBM), 256, GEMM_SMEM>>>(
        Xh, Xl, Woh, Wol, out);
}